// round 17
// baseline (speedup 1.0000x reference)
#include <cuda_runtime.h>
#include <cuda_fp16.h>
#include <math.h>
#include <stdint.h>

// Problem constants
#define NP_   1024
#define MNP_  4096
#define BS_   4
#define DIM_  512
#define NH_   8
#define DH_   64
#define TOPK_ 32

#define MROWS_Q  (NP_*BS_)                 // 4096
#define MROWS_KV (MNP_*BS_)                // 16384
#define MTOT     (MROWS_Q + 2*MROWS_KV)    // 36864

// ---------------------------------------------------------------------------
// Scratch (device globals; no allocation allowed)
// ---------------------------------------------------------------------------
__device__ __half g_a16[(size_t)MTOT * DIM_];      // q|k|v rows in fp16
__device__ __half g_w16[3 * DIM_ * DIM_];          // W1|W2|W3 in fp16
__device__ __half g_proj[(size_t)MTOT * DIM_];     // projections in fp16

// ---------------------------------------------------------------------------
// Helpers
// ---------------------------------------------------------------------------
__device__ __forceinline__ uint32_t smem_u32(const void* p) {
    uint32_t a;
    asm("{ .reg .u64 t; cvta.to.shared.u64 t, %1; cvt.u32.u64 %0, t; }"
        : "=r"(a) : "l"(p));
    return a;
}

__device__ __forceinline__ void cp16(uint32_t dst, const void* src) {
    asm volatile("cp.async.cg.shared.global [%0], [%1], 16;\n"
                 :: "r"(dst), "l"(src) : "memory");
}

__device__ __forceinline__ uint32_t swz(uint32_t o) { return o ^ ((o >> 3) & 0x70); }

__device__ __forceinline__ void ldsm4(uint32_t* f, uint32_t addr) {
    asm volatile("ldmatrix.sync.aligned.m8n8.x4.shared.b16 {%0,%1,%2,%3}, [%4];"
                 : "=r"(f[0]), "=r"(f[1]), "=r"(f[2]), "=r"(f[3]) : "r"(addr));
}

__device__ __forceinline__ void mma16816(float* d, const uint32_t* a,
                                         const uint32_t* b) {
    asm volatile(
        "mma.sync.aligned.m16n8k16.row.col.f32.f16.f16.f32 "
        "{%0,%1,%2,%3}, {%4,%5,%6,%7}, {%8,%9}, {%0,%1,%2,%3};"
        : "+f"(d[0]), "+f"(d[1]), "+f"(d[2]), "+f"(d[3])
        : "r"(a[0]), "r"(a[1]), "r"(a[2]), "r"(a[3]), "r"(b[0]), "r"(b[1]));
}

// ---------------------------------------------------------------------------
// Convert fp32 -> fp16 (RN): q|k|v -> g_a16, W1|W2|W3 -> g_w16.
// ---------------------------------------------------------------------------
#define R_Q  (MROWS_Q * DIM_ / 4)
#define R_K  (R_Q + MROWS_KV * DIM_ / 4)
#define R_V  (R_K + MROWS_KV * DIM_ / 4)
#define R_W1 (R_V + DIM_ * DIM_ / 4)
#define R_W2 (R_W1 + DIM_ * DIM_ / 4)
#define R_W3 (R_W2 + DIM_ * DIM_ / 4)             // 4915200 float4 total

__global__ __launch_bounds__(256)
void cvt_half(const float* __restrict__ q, const float* __restrict__ k,
              const float* __restrict__ v, const float* __restrict__ W1,
              const float* __restrict__ W2, const float* __restrict__ W3,
              __half* __restrict__ a16, __half* __restrict__ w16) {
    const int i = (blockIdx.x * 256 + threadIdx.x) * 2;   // float4 index
    if (i >= R_W3) return;
    const float* src;
    __half* dst;
    size_t si, di;
    if (i < R_V) {
        di = (size_t)i;
        dst = a16;
        if (i < R_Q)      { src = q; si = (size_t)i; }
        else if (i < R_K) { src = k; si = (size_t)(i - R_Q); }
        else              { src = v; si = (size_t)(i - R_K); }
    } else {
        di = (size_t)(i - R_V);
        dst = w16;
        if (i < R_W1)      { src = W1; si = (size_t)(i - R_V); }
        else if (i < R_W2) { src = W2; si = (size_t)(i - R_W1); }
        else               { src = W3; si = (size_t)(i - R_W2); }
    }
    float4 x0 = ((const float4*)src)[si];
    float4 x1 = ((const float4*)src)[si + 1];
    float val[8] = {x0.x, x0.y, x0.z, x0.w, x1.x, x1.y, x1.z, x1.w};
    __half h[8];
#pragma unroll
    for (int j = 0; j < 8; j++) h[j] = __float2half_rn(val[j]);
    *(uint4*)(dst + 4 * di) = *(uint4*)h;
}

// ---------------------------------------------------------------------------
// Single-pass fp16 GEMM: proj = A*W^T + bias, output stored as fp16.
// CTA tile 128x128, K-chunk 64 halves (SW128), 8 chunks, 3-stage cp.async.
// ---------------------------------------------------------------------------
#define KC       64
#define NCHUNK   8
#define STAGES   3
#define A_BYTES  (128 * 128)
#define B_BYTES  (128 * 128)
#define STG_B    (A_BYTES + B_BYTES)
#define GEMM_SMEM (STAGES * STG_B)           // 96KB

__global__ __launch_bounds__(256, 2)
void gemm_f16(const __half* __restrict__ a16, const __half* __restrict__ w16,
              const float* __restrict__ b1, const float* __restrict__ b2,
              const float* __restrict__ b3, __half* __restrict__ out) {
    extern __shared__ __align__(1024) char smem[];
    const uint32_t sbase = smem_u32(smem);
    const int tid = threadIdx.x;
    const int wid = tid >> 5;
    const int lane = tid & 31;
    const int wm = wid & 3;
    const int wn = wid >> 2;

    const int n0blk = blockIdx.x * 128;
    const int mt = blockIdx.y;
    const int widx = (mt < 32) ? 0 : (mt < 160) ? 1 : 2;
    const float* bias = (widx == 0) ? b1 : (widx == 1) ? b2 : b3;
    const __half* Wp = w16 + (size_t)widx * DIM_ * DIM_;
    const size_t arow0 = (size_t)mt * 128;

    float acc[2][8][4];
#pragma unroll
    for (int i = 0; i < 2; i++)
#pragma unroll
        for (int j = 0; j < 8; j++)
#pragma unroll
            for (int r = 0; r < 4; r++) acc[i][j][r] = 0.f;

    auto load_chunk = [&](int c, int s) {
        const int kk = c * KC;
        const uint32_t a_s = sbase + s * STG_B;
        const uint32_t b_s = a_s + A_BYTES;
#pragma unroll
        for (int i = 0; i < 4; i++) {
            int u = tid + (i << 8);
            int r = u >> 3, j = u & 7;
            cp16(a_s + swz(r * 128 + j * 16),
                 a16 + (arow0 + r) * DIM_ + kk + j * 8);
        }
#pragma unroll
        for (int i = 0; i < 4; i++) {
            int u = tid + (i << 8);
            int r = u >> 3, j = u & 7;
            cp16(b_s + swz(r * 128 + j * 16),
                 Wp + (size_t)(n0blk + r) * DIM_ + kk + j * 8);
        }
        asm volatile("cp.async.commit_group;\n" ::: "memory");
    };

    load_chunk(0, 0);
    load_chunk(1, 1);

    const int a_row = wm * 32 + (lane & 15);
    const int a_ch  = (lane >> 4);
    const int b_row = wn * 64 + (lane & 7) + ((lane >> 4) << 3);
    const int b_ch  = ((lane >> 3) & 1);

#pragma unroll 1
    for (int c = 0; c < NCHUNK; ++c) {
        const int s = c % STAGES;
        if (c == NCHUNK - 1)
            asm volatile("cp.async.wait_group 0;\n" ::: "memory");
        else
            asm volatile("cp.async.wait_group 1;\n" ::: "memory");
        __syncthreads();
        if (c + 2 < NCHUNK) load_chunk(c + 2, (c + 2) % STAGES);

        const uint32_t a_s = sbase + s * STG_B;
        const uint32_t b_s = a_s + A_BYTES;
#pragma unroll
        for (int ks = 0; ks < 4; ks++) {
            const int c0 = ks * 2;
            uint32_t af[2][4];
#pragma unroll
            for (int i = 0; i < 2; i++)
                ldsm4(af[i], a_s + swz((a_row + i * 16) * 128 + (c0 + a_ch) * 16));
            uint32_t bf[4][4];
#pragma unroll
            for (int j = 0; j < 4; j++)
                ldsm4(bf[j], b_s + swz((b_row + j * 16) * 128 + (c0 + b_ch) * 16));
#pragma unroll
            for (int i = 0; i < 2; i++)
#pragma unroll
                for (int j = 0; j < 4; j++) {
                    mma16816(acc[i][2 * j],     af[i], &bf[j][0]);
                    mma16816(acc[i][2 * j + 1], af[i], &bf[j][2]);
                }
        }
    }

    // epilogue -> fp16 (bias added in fp32, then RN convert)
    const int lr = lane >> 2;
    const int lc = (lane & 3) * 2;
#pragma unroll
    for (int i = 0; i < 2; i++) {
        const size_t row0 = arow0 + wm * 32 + i * 16 + lr;
#pragma unroll
        for (int j = 0; j < 8; j++) {
            const int col = n0blk + wn * 64 + j * 8 + lc;
            const float bx = bias[col], by = bias[col + 1];
            __half2 o0 = __floats2half2_rn(acc[i][j][0] + bx, acc[i][j][1] + by);
            __half2 o1 = __floats2half2_rn(acc[i][j][2] + bx, acc[i][j][3] + by);
            *(__half2*)(out + row0 * DIM_ + col) = o0;
            *(__half2*)(out + (row0 + 8) * DIM_ + col) = o1;
        }
    }
}

// ---------------------------------------------------------------------------
// Sparse attention over fp16 projections.
// Phase 1: warp w scores candidates {w, w+8, w+16, w+24}; lane l pass j
//          loads uint4 (8 halves) at half-offset 8*(j*32+l) — each 8-lane
//          group covers exactly one head (head = j*4 + l/8), reduce with
//          3 shfls. Phase 2: per-head warp softmax. Phase 3: V accumulate.
// Output fp32.
// ---------------------------------------------------------------------------
__global__ __launch_bounds__(256)
void attn_kernel(const __half* __restrict__ qh, const __half* __restrict__ kh,
                 const __half* __restrict__ vh, const int* __restrict__ rns,
                 float* __restrict__ out) {
    __shared__ float sq[DIM_];
    __shared__ int srow[TOPK_];
    __shared__ int svrow[TOPK_];
    __shared__ float sscore[NH_][TOPK_];

    const int n = blockIdx.x;
    const int b = blockIdx.y;
    const int tid = threadIdx.x;
    const int lane = tid & 31;
    const int wid = tid >> 5;

    // stage q row (fp16 -> fp32 smem): 256 threads x 1 half2
    {
        const __half2 qv = ((const __half2*)(qh + (size_t)(n * BS_ + b) * DIM_))[tid];
        const float2 qf = __half22float2(qv);
        sq[2 * tid]     = qf.x;
        sq[2 * tid + 1] = qf.y;
    }
    if (tid < TOPK_)
        srow[tid] = rns[((size_t)b * NP_ + n) * TOPK_ + tid];
    __syncthreads();
    if (tid < TOPK_) {
        const int m = srow[tid];
        bool valid = true;
        for (int j = 0; j < tid; j++)
            if (srow[j] == m) valid = false;
        svrow[tid] = valid ? (m * BS_ + b) : -1;
    }
    __syncthreads();

    // ---- Phase 1: scores ----
#pragma unroll
    for (int cc = 0; cc < 4; cc++) {
        const int c = wid + cc * 8;
        const int r = svrow[c];
        float p[2] = {0.f, 0.f};
        if (r >= 0) {
            const uint4* kp = (const uint4*)(kh + (size_t)r * DIM_);
#pragma unroll
            for (int j = 0; j < 2; j++) {
                const uint4 kv8 = kp[j * 32 + lane];
                const __half2* kh2 = (const __half2*)&kv8;
                const float* qp = sq + 8 * (j * 32 + lane);
                float a = 0.f;
#pragma unroll
                for (int t = 0; t < 4; t++) {
                    const float2 kf = __half22float2(kh2[t]);
                    a = fmaf(kf.x, qp[2 * t], a);
                    a = fmaf(kf.y, qp[2 * t + 1], a);
                }
                p[j] = a;
            }
        }
#pragma unroll
        for (int j = 0; j < 2; j++) {
            p[j] += __shfl_xor_sync(0xffffffffu, p[j], 4);
            p[j] += __shfl_xor_sync(0xffffffffu, p[j], 2);
            p[j] += __shfl_xor_sync(0xffffffffu, p[j], 1);
        }
        if ((lane & 7) == 0) {
            const int hb = lane >> 3;    // 0..3
#pragma unroll
            for (int j = 0; j < 2; j++)
                sscore[j * 4 + hb][c] = (r >= 0) ? p[j] * 0.125f : -INFINITY;
        }
    }
    __syncthreads();

    // ---- Phase 2: per-head softmax (warp = head, lane = candidate) ----
    const int h = wid;
    const float s = sscore[h][lane];
    float mx = s;
#pragma unroll
    for (int o = 16; o; o >>= 1)
        mx = fmaxf(mx, __shfl_xor_sync(0xffffffffu, mx, o));
    float p = (s > -1e30f) ? __expf(s - mx) : 0.f;
    float sum = p;
#pragma unroll
    for (int o = 16; o; o >>= 1)
        sum += __shfl_xor_sync(0xffffffffu, sum, o);
    const float w = p / sum;

    // ---- Phase 3: V accumulate (lane covers 2 dims of head h) ----
    const int rl = svrow[lane];
    float2 acc2 = make_float2(0.f, 0.f);
#pragma unroll
    for (int t = 0; t < TOPK_; t++) {
        const float wt = __shfl_sync(0xffffffffu, w, t);
        const int r = __shfl_sync(0xffffffffu, rl, t);
        if (r >= 0) {
            const __half2 vv =
                ((const __half2*)(vh + (size_t)r * DIM_ + h * DH_))[lane];
            const float2 vf = __half22float2(vv);
            acc2.x = fmaf(wt, vf.x, acc2.x);
            acc2.y = fmaf(wt, vf.y, acc2.y);
        }
    }
    *(float2*)(out + (size_t)(n * BS_ + b) * DIM_ + h * DH_ + lane * 2) = acc2;
}

// ---------------------------------------------------------------------------
extern "C" void kernel_launch(void* const* d_in, const int* in_sizes, int n_in,
                              void* d_out, int out_size) {
    const float* q   = (const float*)d_in[0];
    const float* k   = (const float*)d_in[1];
    const float* v   = (const float*)d_in[2];
    const int*   rns = (const int*)d_in[3];
    const float* W1  = (const float*)d_in[4];
    const float* b1  = (const float*)d_in[5];
    const float* W2  = (const float*)d_in[6];
    const float* b2  = (const float*)d_in[7];
    const float* W3  = (const float*)d_in[8];
    const float* b3  = (const float*)d_in[9];
    float* out = (float*)d_out;

    __half *a16, *w16, *proj;
    cudaGetSymbolAddress((void**)&a16, g_a16);
    cudaGetSymbolAddress((void**)&w16, g_w16);
    cudaGetSymbolAddress((void**)&proj, g_proj);

    cudaFuncSetAttribute(gemm_f16, cudaFuncAttributeMaxDynamicSharedMemorySize,
                         GEMM_SMEM);

    const size_t offK = (size_t)MROWS_Q * DIM_;
    const size_t offV = offK + (size_t)MROWS_KV * DIM_;

    cvt_half<<<(R_W3 / 2 + 255) / 256, 256>>>(q, k, v, W1, W2, W3, a16, w16);

    gemm_f16<<<dim3(4, 288), 256, GEMM_SMEM>>>(a16, w16, b1, b2, b3, proj);

    attn_kernel<<<dim3(NP_, BS_), 256>>>(proj, proj + offK, proj + offV, rns, out);
}